// round 1
// baseline (speedup 1.0000x reference)
#include <cuda_runtime.h>
#include <math.h>

// Problem constants
#define NNODES 100000
#define NEDGES 1600000
#define ETOT   (NEDGES + NNODES)   // edges + self loops
#define KDIM   256
#define LD1    128                 // HEADS*HID = 4*32
#define LD2    160                 // HEADS2*NCLASS = 4*40
#define LDCAT  256
#define NEG_SLOPE 0.2f

// ---------------- scratch (static device globals; no allocations) --------
__device__ __align__(16) float g_bufA[(size_t)NNODES * LD2];   // h1_0 then h2
__device__ __align__(16) float g_bufB[(size_t)NNODES * LD1];   // h1_1
__device__ __align__(16) float g_xcat[(size_t)NNODES * LDCAT]; // concat(elu out1_0, elu out1_1)
__device__ __align__(16) float g_pas0[NNODES * 4];
__device__ __align__(16) float g_pad0[NNODES * 4];
__device__ __align__(16) float g_pas1[NNODES * 4];
__device__ __align__(16) float g_pad1[NNODES * 4];
__device__ int g_cnt[NNODES];
__device__ int g_incl[NNODES];
__device__ int g_bsum[128];
__device__ int g_rowptr[NNODES + 1];
__device__ int g_cursor[NNODES];
__device__ int g_colidx[ETOT];

// ---------------- helpers ----------------
__device__ __forceinline__ float lrelu(float x) { return fmaxf(x, NEG_SLOPE * x); }
__device__ __forceinline__ float eluf(float x)  { return x > 0.0f ? x : expm1f(x); }

// ---------------- CSR build ----------------
__global__ void k_init_cnt(int* cnt) {
    int i = blockIdx.x * blockDim.x + threadIdx.x;
    if (i < NNODES) cnt[i] = 1;   // self-loop
}

__global__ void k_hist(const int* __restrict__ dst, int* cnt) {
    int e = blockIdx.x * blockDim.x + threadIdx.x;
    if (e < NEDGES) atomicAdd(&cnt[dst[e]], 1);
}

__global__ void k_scan1(const int* __restrict__ cnt, int* incl, int* bsum) {
    __shared__ int sh[1024];
    int i = blockIdx.x * 1024 + threadIdx.x;
    int v = (i < NNODES) ? cnt[i] : 0;
    sh[threadIdx.x] = v;
    __syncthreads();
    for (int off = 1; off < 1024; off <<= 1) {
        int t = (threadIdx.x >= off) ? sh[threadIdx.x - off] : 0;
        __syncthreads();
        sh[threadIdx.x] += t;
        __syncthreads();
    }
    if (i < NNODES) incl[i] = sh[threadIdx.x];
    if (threadIdx.x == 1023) bsum[blockIdx.x] = sh[1023];
}

#define NB_SCAN ((NNODES + 1023) / 1024)   // 98

__global__ void k_scan2(int* bsum) {
    __shared__ int sh[128];
    int v = (threadIdx.x < NB_SCAN) ? bsum[threadIdx.x] : 0;
    sh[threadIdx.x] = v;
    __syncthreads();
    for (int off = 1; off < 128; off <<= 1) {
        int t = (threadIdx.x >= off) ? sh[threadIdx.x - off] : 0;
        __syncthreads();
        sh[threadIdx.x] += t;
        __syncthreads();
    }
    if (threadIdx.x < NB_SCAN) bsum[threadIdx.x] = sh[threadIdx.x];
}

__global__ void k_scan3(const int* __restrict__ incl, const int* __restrict__ bsum,
                        const int* __restrict__ cnt, int* rowptr, int* cursor) {
    int i = blockIdx.x * blockDim.x + threadIdx.x;
    if (i >= NNODES) return;
    int blk = i >> 10;
    int off = blk ? bsum[blk - 1] : 0;
    int inc = incl[i] + off;
    int start = inc - cnt[i];
    rowptr[i] = start;
    cursor[i] = start;
    if (i == NNODES - 1) rowptr[NNODES] = inc;
}

__global__ void k_scatter(const int* __restrict__ src, const int* __restrict__ dst,
                          int* cursor, int* colidx) {
    int e = blockIdx.x * blockDim.x + threadIdx.x;
    if (e < NEDGES) {
        int d = dst[e];
        int p = atomicAdd(&cursor[d], 1);
        colidx[p] = src[e];
    } else if (e < ETOT) {
        int n = e - NEDGES;
        int p = atomicAdd(&cursor[n], 1);
        colidx[p] = n;
    }
}

// ---------------- fp32 SGEMM: C[M,Ncols] = A[M,K] * B[K,Ncols] ----------------
#define BM 128
#define BN 128
#define BK 16

__global__ void __launch_bounds__(256) k_sgemm(
    const float* __restrict__ A, const float* __restrict__ B, float* __restrict__ C,
    int M, int K, int Ncols, int lda, int ldb, int ldc)
{
    __shared__ float As[BM][BK + 1];
    __shared__ float Bs[BK][BN];
    int tid = threadIdx.x;
    int tx = tid & 15, ty = tid >> 4;
    int m0 = blockIdx.x * BM;
    int n0 = blockIdx.y * BN;

    int arow = tid >> 2;
    int acol = (tid & 3) * 4;
    int brow = tid >> 5;
    int bcol = (tid & 31) * 4;

    float acc[8][8];
#pragma unroll
    for (int i = 0; i < 8; i++)
#pragma unroll
        for (int j = 0; j < 8; j++) acc[i][j] = 0.0f;

    for (int k0 = 0; k0 < K; k0 += BK) {
#pragma unroll
        for (int r = 0; r < 2; r++) {
            int row = arow + r * 64;
            float4 av = make_float4(0.f, 0.f, 0.f, 0.f);
            if (m0 + row < M)
                av = *(const float4*)(A + (size_t)(m0 + row) * lda + k0 + acol);
            As[row][acol + 0] = av.x;
            As[row][acol + 1] = av.y;
            As[row][acol + 2] = av.z;
            As[row][acol + 3] = av.w;
        }
#pragma unroll
        for (int r = 0; r < 2; r++) {
            int row = brow + r * 8;
            float4 bv = make_float4(0.f, 0.f, 0.f, 0.f);
            if (n0 + bcol < Ncols)
                bv = *(const float4*)(B + (size_t)(k0 + row) * ldb + n0 + bcol);
            *(float4*)&Bs[row][bcol] = bv;
        }
        __syncthreads();
#pragma unroll
        for (int k = 0; k < BK; k++) {
            float ar[8], br[8];
#pragma unroll
            for (int i = 0; i < 8; i++) ar[i] = As[ty * 8 + i][k];
#pragma unroll
            for (int j = 0; j < 8; j++) br[j] = Bs[k][tx * 8 + j];
#pragma unroll
            for (int i = 0; i < 8; i++)
#pragma unroll
                for (int j = 0; j < 8; j++) acc[i][j] += ar[i] * br[j];
        }
        __syncthreads();
    }

#pragma unroll
    for (int i = 0; i < 8; i++) {
        int row = m0 + ty * 8 + i;
        if (row >= M) break;
        float* crow = C + (size_t)row * ldc;
#pragma unroll
        for (int j = 0; j < 8; j += 4) {
            int col = n0 + tx * 8 + j;
            if (col < Ncols)
                *(float4*)(crow + col) =
                    make_float4(acc[i][j], acc[i][j + 1], acc[i][j + 2], acc[i][j + 3]);
        }
    }
}

// ---------------- per-node attention coefficients (warp per node) ----------------
__global__ void k_alpha(const float* __restrict__ htab, int ld, int cdim,
                        const float* __restrict__ asrc, const float* __restrict__ adst,
                        float* __restrict__ out_s, float* __restrict__ out_d)
{
    int warp = (blockIdx.x * blockDim.x + threadIdx.x) >> 5;
    int lane = threadIdx.x & 31;
    if (warp >= NNODES) return;
    const float* hrow = htab + (size_t)warp * ld;
#pragma unroll
    for (int h = 0; h < 4; h++) {
        float s = 0.f, d = 0.f;
        for (int c = lane; c < cdim; c += 32) {
            float v = hrow[h * cdim + c];
            s += v * asrc[h * cdim + c];
            d += v * adst[h * cdim + c];
        }
#pragma unroll
        for (int o = 16; o; o >>= 1) {
            s += __shfl_xor_sync(0xffffffffu, s, o);
            d += __shfl_xor_sync(0xffffffffu, d, o);
        }
        if (lane == 0) {
            out_s[warp * 4 + h] = s;
            out_d[warp * 4 + h] = d;
        }
    }
}

// ---------------- layer-1 aggregation (warp per dst node), fused bias+ELU ----------------
__global__ void k_agg1(const float* __restrict__ htab, const float* __restrict__ as,
                       const float* __restrict__ ad, const float* __restrict__ bias,
                       const int* __restrict__ rowptr, const int* __restrict__ colidx,
                       float* __restrict__ out, int out_off)
{
    int n = (blockIdx.x * blockDim.x + threadIdx.x) >> 5;
    int lane = threadIdx.x & 31;
    if (n >= NNODES) return;
    int s0 = rowptr[n], s1 = rowptr[n + 1];
    float4 ad4 = ((const float4*)ad)[n];

    // pass 1: per-head max logit
    float m0 = -1e30f, m1 = -1e30f, m2 = -1e30f, m3 = -1e30f;
    for (int i = s0 + lane; i < s1; i += 32) {
        int src = colidx[i];
        float4 a = ((const float4*)as)[src];
        m0 = fmaxf(m0, lrelu(a.x + ad4.x));
        m1 = fmaxf(m1, lrelu(a.y + ad4.y));
        m2 = fmaxf(m2, lrelu(a.z + ad4.z));
        m3 = fmaxf(m3, lrelu(a.w + ad4.w));
    }
#pragma unroll
    for (int o = 16; o; o >>= 1) {
        m0 = fmaxf(m0, __shfl_xor_sync(0xffffffffu, m0, o));
        m1 = fmaxf(m1, __shfl_xor_sync(0xffffffffu, m1, o));
        m2 = fmaxf(m2, __shfl_xor_sync(0xffffffffu, m2, o));
        m3 = fmaxf(m3, __shfl_xor_sync(0xffffffffu, m3, o));
    }

    // pass 2: weighted aggregation (unnormalized) + denominator
    float d0 = 0.f, d1 = 0.f, d2 = 0.f, d3 = 0.f;
    float acc0 = 0.f, acc1 = 0.f, acc2 = 0.f, acc3 = 0.f;
    int i = s0;
    for (; i + 1 < s1; i += 2) {
        int srcA = colidx[i];
        int srcB = colidx[i + 1];
        float4 aA = ((const float4*)as)[srcA];
        float4 aB = ((const float4*)as)[srcB];
        const float* hA = htab + (size_t)srcA * LD1;
        const float* hB = htab + (size_t)srcB * LD1;
        float vA0 = hA[lane], vA1 = hA[32 + lane], vA2 = hA[64 + lane], vA3 = hA[96 + lane];
        float vB0 = hB[lane], vB1 = hB[32 + lane], vB2 = hB[64 + lane], vB3 = hB[96 + lane];
        float wA0 = __expf(lrelu(aA.x + ad4.x) - m0);
        float wA1 = __expf(lrelu(aA.y + ad4.y) - m1);
        float wA2 = __expf(lrelu(aA.z + ad4.z) - m2);
        float wA3 = __expf(lrelu(aA.w + ad4.w) - m3);
        float wB0 = __expf(lrelu(aB.x + ad4.x) - m0);
        float wB1 = __expf(lrelu(aB.y + ad4.y) - m1);
        float wB2 = __expf(lrelu(aB.z + ad4.z) - m2);
        float wB3 = __expf(lrelu(aB.w + ad4.w) - m3);
        d0 += wA0 + wB0; d1 += wA1 + wB1; d2 += wA2 + wB2; d3 += wA3 + wB3;
        acc0 += wA0 * vA0 + wB0 * vB0;
        acc1 += wA1 * vA1 + wB1 * vB1;
        acc2 += wA2 * vA2 + wB2 * vB2;
        acc3 += wA3 * vA3 + wB3 * vB3;
    }
    if (i < s1) {
        int src = colidx[i];
        float4 a = ((const float4*)as)[src];
        const float* hr = htab + (size_t)src * LD1;
        float w0 = __expf(lrelu(a.x + ad4.x) - m0);
        float w1 = __expf(lrelu(a.y + ad4.y) - m1);
        float w2 = __expf(lrelu(a.z + ad4.z) - m2);
        float w3 = __expf(lrelu(a.w + ad4.w) - m3);
        d0 += w0; d1 += w1; d2 += w2; d3 += w3;
        acc0 += w0 * hr[lane];
        acc1 += w1 * hr[32 + lane];
        acc2 += w2 * hr[64 + lane];
        acc3 += w3 * hr[96 + lane];
    }

    float* orow = out + (size_t)n * LDCAT + out_off;
    orow[lane]      = eluf(acc0 / (d0 + 1e-16f) + bias[lane]);
    orow[32 + lane] = eluf(acc1 / (d1 + 1e-16f) + bias[32 + lane]);
    orow[64 + lane] = eluf(acc2 / (d2 + 1e-16f) + bias[64 + lane]);
    orow[96 + lane] = eluf(acc3 / (d3 + 1e-16f) + bias[96 + lane]);
}

// ---------------- layer-2 aggregation (warp per dst node), head-mean + bias ----------------
__global__ void k_agg2(const float* __restrict__ htab, const float* __restrict__ as,
                       const float* __restrict__ ad, const float* __restrict__ bias,
                       const int* __restrict__ rowptr, const int* __restrict__ colidx,
                       float* __restrict__ out)
{
    int n = (blockIdx.x * blockDim.x + threadIdx.x) >> 5;
    int lane = threadIdx.x & 31;
    if (n >= NNODES) return;
    int s0 = rowptr[n], s1 = rowptr[n + 1];
    float4 ad4 = ((const float4*)ad)[n];

    float m0 = -1e30f, m1 = -1e30f, m2 = -1e30f, m3 = -1e30f;
    for (int i = s0 + lane; i < s1; i += 32) {
        int src = colidx[i];
        float4 a = ((const float4*)as)[src];
        m0 = fmaxf(m0, lrelu(a.x + ad4.x));
        m1 = fmaxf(m1, lrelu(a.y + ad4.y));
        m2 = fmaxf(m2, lrelu(a.z + ad4.z));
        m3 = fmaxf(m3, lrelu(a.w + ad4.w));
    }
#pragma unroll
    for (int o = 16; o; o >>= 1) {
        m0 = fmaxf(m0, __shfl_xor_sync(0xffffffffu, m0, o));
        m1 = fmaxf(m1, __shfl_xor_sync(0xffffffffu, m1, o));
        m2 = fmaxf(m2, __shfl_xor_sync(0xffffffffu, m2, o));
        m3 = fmaxf(m3, __shfl_xor_sync(0xffffffffu, m3, o));
    }

    float d0 = 0.f, d1 = 0.f, d2 = 0.f, d3 = 0.f;
    float accA0 = 0.f, accA1 = 0.f, accA2 = 0.f, accA3 = 0.f;   // channels 0..31 of each head
    float accB0 = 0.f, accB1 = 0.f, accB2 = 0.f, accB3 = 0.f;   // channels 32..39 (lane < 8)
    bool hasB = lane < 8;
    for (int i = s0; i < s1; i++) {
        int src = colidx[i];
        float4 a = ((const float4*)as)[src];
        const float* hr = htab + (size_t)src * LD2;
        float vA0 = hr[lane], vA1 = hr[40 + lane], vA2 = hr[80 + lane], vA3 = hr[120 + lane];
        float vB0 = 0.f, vB1 = 0.f, vB2 = 0.f, vB3 = 0.f;
        if (hasB) {
            vB0 = hr[32 + lane]; vB1 = hr[72 + lane]; vB2 = hr[112 + lane]; vB3 = hr[152 + lane];
        }
        float w0 = __expf(lrelu(a.x + ad4.x) - m0);
        float w1 = __expf(lrelu(a.y + ad4.y) - m1);
        float w2 = __expf(lrelu(a.z + ad4.z) - m2);
        float w3 = __expf(lrelu(a.w + ad4.w) - m3);
        d0 += w0; d1 += w1; d2 += w2; d3 += w3;
        accA0 += w0 * vA0; accA1 += w1 * vA1; accA2 += w2 * vA2; accA3 += w3 * vA3;
        accB0 += w0 * vB0; accB1 += w1 * vB1; accB2 += w2 * vB2; accB3 += w3 * vB3;
    }
    float i0 = 1.f / (d0 + 1e-16f), i1 = 1.f / (d1 + 1e-16f);
    float i2 = 1.f / (d2 + 1e-16f), i3 = 1.f / (d3 + 1e-16f);
    float* orow = out + (size_t)n * 40;
    orow[lane] = 0.25f * (accA0 * i0 + accA1 * i1 + accA2 * i2 + accA3 * i3) + bias[lane];
    if (hasB)
        orow[32 + lane] =
            0.25f * (accB0 * i0 + accB1 * i1 + accB2 * i2 + accB3 * i3) + bias[32 + lane];
}

// ---------------- launch ----------------
extern "C" void kernel_launch(void* const* d_in, const int* in_sizes, int n_in,
                              void* d_out, int out_size)
{
    const float* x0    = (const float*)d_in[0];
    const float* x1    = (const float*)d_in[1];
    const int*   ei    = (const int*)d_in[2];
    const float* W1_0  = (const float*)d_in[3];
    const float* aS1_0 = (const float*)d_in[4];
    const float* aD1_0 = (const float*)d_in[5];
    const float* b1_0  = (const float*)d_in[6];
    const float* W1_1  = (const float*)d_in[7];
    const float* aS1_1 = (const float*)d_in[8];
    const float* aD1_1 = (const float*)d_in[9];
    const float* b1_1  = (const float*)d_in[10];
    const float* W2    = (const float*)d_in[11];
    const float* aS2   = (const float*)d_in[12];
    const float* aD2   = (const float*)d_in[13];
    const float* b2    = (const float*)d_in[14];
    float* out = (float*)d_out;

    const int* srcp = ei;
    const int* dstp = ei + NEDGES;

    float *bufA, *bufB, *xcat, *pas0, *pad0, *pas1, *pad1;
    int *cnt, *incl, *bsum, *rowptr, *cursor, *colidx;
    cudaGetSymbolAddress((void**)&bufA, g_bufA);
    cudaGetSymbolAddress((void**)&bufB, g_bufB);
    cudaGetSymbolAddress((void**)&xcat, g_xcat);
    cudaGetSymbolAddress((void**)&pas0, g_pas0);
    cudaGetSymbolAddress((void**)&pad0, g_pad0);
    cudaGetSymbolAddress((void**)&pas1, g_pas1);
    cudaGetSymbolAddress((void**)&pad1, g_pad1);
    cudaGetSymbolAddress((void**)&cnt, g_cnt);
    cudaGetSymbolAddress((void**)&incl, g_incl);
    cudaGetSymbolAddress((void**)&bsum, g_bsum);
    cudaGetSymbolAddress((void**)&rowptr, g_rowptr);
    cudaGetSymbolAddress((void**)&cursor, g_cursor);
    cudaGetSymbolAddress((void**)&colidx, g_colidx);

    // CSR build (includes self-loops)
    k_init_cnt<<<(NNODES + 255) / 256, 256>>>(cnt);
    k_hist<<<(NEDGES + 255) / 256, 256>>>(dstp, cnt);
    k_scan1<<<NB_SCAN, 1024>>>(cnt, incl, bsum);
    k_scan2<<<1, 128>>>(bsum);
    k_scan3<<<(NNODES + 255) / 256, 256>>>(incl, bsum, cnt, rowptr, cursor);
    k_scatter<<<(ETOT + 255) / 256, 256>>>(srcp, dstp, cursor, colidx);

    dim3 blk(256);
    dim3 g1((NNODES + BM - 1) / BM, 1);
    // layer-1 GEMMs
    k_sgemm<<<g1, blk>>>(x0, W1_0, bufA, NNODES, KDIM, LD1, KDIM, LD1, LD1);
    k_sgemm<<<g1, blk>>>(x1, W1_1, bufB, NNODES, KDIM, LD1, KDIM, LD1, LD1);
    // attention coefficients
    k_alpha<<<12500, 256>>>(bufA, LD1, 32, aS1_0, aD1_0, pas0, pad0);
    k_alpha<<<12500, 256>>>(bufB, LD1, 32, aS1_1, aD1_1, pas1, pad1);
    // layer-1 aggregation (+bias +ELU), write into concat buffer
    k_agg1<<<12500, 256>>>(bufA, pas0, pad0, b1_0, rowptr, colidx, xcat, 0);
    k_agg1<<<12500, 256>>>(bufB, pas1, pad1, b1_1, rowptr, colidx, xcat, 128);
    // layer-2 GEMM (reuse bufA as h2 [N,160])
    dim3 g2((NNODES + BM - 1) / BM, (LD2 + BN - 1) / BN);
    k_sgemm<<<g2, blk>>>(xcat, W2, bufA, NNODES, KDIM, LD2, LDCAT, LD2, LD2);
    k_alpha<<<12500, 256>>>(bufA, LD2, 40, aS2, aD2, pas0, pad0);
    // layer-2 aggregation: head mean + bias -> d_out
    k_agg2<<<12500, 256>>>(bufA, pas0, pad0, b2, rowptr, colidx, out);
}

// round 3
// speedup vs baseline: 1.1486x; 1.1486x over previous
#include <cuda_runtime.h>
#include <math.h>
#include <stdint.h>

// Problem constants
#define NNODES 100000
#define NEDGES 1600000
#define ETOT   (NEDGES + NNODES)   // edges + self loops
#define KDIM   256
#define LD1    128                 // HEADS*HID = 4*32
#define LD2    160                 // HEADS2*NCLASS = 4*40
#define LDCAT  256
#define NEG_SLOPE 0.2f

// ---------------- scratch (static device globals; no allocations) --------
__device__ __align__(16) float g_bufA[(size_t)NNODES * LD2];   // h1_0 then h2
__device__ __align__(16) float g_bufB[(size_t)NNODES * LD1];   // h1_1
__device__ __align__(16) float g_xcat[(size_t)NNODES * LDCAT]; // concat(elu out1_0, elu out1_1)
__device__ __align__(16) float g_pas0[NNODES * 4];
__device__ __align__(16) float g_pad0[NNODES * 4];
__device__ __align__(16) float g_pas1[NNODES * 4];
__device__ __align__(16) float g_pad1[NNODES * 4];
__device__ int g_cnt[NNODES];
__device__ int g_incl[NNODES];
__device__ int g_bsum[128];
__device__ int g_rowptr[NNODES + 1];
__device__ int g_cursor[NNODES];
__device__ int g_colidx[ETOT];

// ---------------- helpers ----------------
__device__ __forceinline__ float lrelu(float x) { return fmaxf(x, NEG_SLOPE * x); }
__device__ __forceinline__ float eluf(float x)  { return x > 0.0f ? x : expm1f(x); }

// ---------------- CSR build ----------------
__global__ void k_init_cnt(int* cnt) {
    int i = blockIdx.x * blockDim.x + threadIdx.x;
    if (i < NNODES) cnt[i] = 1;   // self-loop
}

__global__ void k_hist(const int* __restrict__ dst, int* cnt) {
    int e = blockIdx.x * blockDim.x + threadIdx.x;
    if (e < NEDGES) atomicAdd(&cnt[dst[e]], 1);
}

__global__ void k_scan1(const int* __restrict__ cnt, int* incl, int* bsum) {
    __shared__ int sh[1024];
    int i = blockIdx.x * 1024 + threadIdx.x;
    int v = (i < NNODES) ? cnt[i] : 0;
    sh[threadIdx.x] = v;
    __syncthreads();
    for (int off = 1; off < 1024; off <<= 1) {
        int t = (threadIdx.x >= off) ? sh[threadIdx.x - off] : 0;
        __syncthreads();
        sh[threadIdx.x] += t;
        __syncthreads();
    }
    if (i < NNODES) incl[i] = sh[threadIdx.x];
    if (threadIdx.x == 1023) bsum[blockIdx.x] = sh[1023];
}

#define NB_SCAN ((NNODES + 1023) / 1024)   // 98

__global__ void k_scan2(int* bsum) {
    __shared__ int sh[128];
    int v = (threadIdx.x < NB_SCAN) ? bsum[threadIdx.x] : 0;
    sh[threadIdx.x] = v;
    __syncthreads();
    for (int off = 1; off < 128; off <<= 1) {
        int t = (threadIdx.x >= off) ? sh[threadIdx.x - off] : 0;
        __syncthreads();
        sh[threadIdx.x] += t;
        __syncthreads();
    }
    if (threadIdx.x < NB_SCAN) bsum[threadIdx.x] = sh[threadIdx.x];
}

__global__ void k_scan3(const int* __restrict__ incl, const int* __restrict__ bsum,
                        const int* __restrict__ cnt, int* rowptr, int* cursor) {
    int i = blockIdx.x * blockDim.x + threadIdx.x;
    if (i >= NNODES) return;
    int blk = i >> 10;
    int off = blk ? bsum[blk - 1] : 0;
    int inc = incl[i] + off;
    int start = inc - cnt[i];
    rowptr[i] = start;
    cursor[i] = start;
    if (i == NNODES - 1) rowptr[NNODES] = inc;
}

__global__ void k_scatter(const int* __restrict__ src, const int* __restrict__ dst,
                          int* cursor, int* colidx) {
    int e = blockIdx.x * blockDim.x + threadIdx.x;
    if (e < NEDGES) {
        int d = dst[e];
        int p = atomicAdd(&cursor[d], 1);
        colidx[p] = src[e];
    } else if (e < ETOT) {
        int n = e - NEDGES;
        int p = atomicAdd(&cursor[n], 1);
        colidx[p] = n;
    }
}

// ================= 3xTF32 tensor-core GEMM (fp32-accurate) =================
// C[M,N] = A[M,K] * B[K,N]. Each operand split hi/lo in tf32;
// acc += Ahi*Bhi + Ahi*Blo + Alo*Bhi  (error ~2^-22, ~fp32).
// Block tile 128x128, BK=16, 8 warps (4x2), warp tile 32x64, 2-stage cp.async.

#define GBM 128
#define GBN 128
#define GBK 16

struct GemmStage {
    float As[GBM][GBK + 4];    // +4 pad: conflict-free fragment loads
    float Bs[GBK][GBN + 8];    // +8 pad: conflict-free fragment loads
};

__device__ __forceinline__ void cpasync16(void* dst, const void* src, bool pred) {
    uint32_t d = (uint32_t)__cvta_generic_to_shared(dst);
    int sz = pred ? 16 : 0;
    asm volatile("cp.async.cg.shared.global [%0], [%1], 16, %2;\n"
                 :: "r"(d), "l"(src), "r"(sz));
}
__device__ __forceinline__ void cp_commit() {
    asm volatile("cp.async.commit_group;\n");
}
template <int NWAIT>
__device__ __forceinline__ void cp_wait() {
    asm volatile("cp.async.wait_group %0;\n" :: "n"(NWAIT));
}

__device__ __forceinline__ uint32_t f2tf32(float x) {
    uint32_t r;
    asm("cvt.rna.tf32.f32 %0, %1;\n" : "=r"(r) : "f"(x));
    return r;
}
__device__ __forceinline__ void split_tf32(float x, uint32_t& hi, uint32_t& lo) {
    hi = f2tf32(x);
    lo = f2tf32(x - __uint_as_float(hi));
}

__device__ __forceinline__ void mma_tf32(float* c, const uint32_t* a, const uint32_t* b) {
    asm volatile(
        "mma.sync.aligned.m16n8k8.row.col.f32.tf32.tf32.f32 "
        "{%0,%1,%2,%3}, {%4,%5,%6,%7}, {%8,%9}, {%0,%1,%2,%3};\n"
        : "+f"(c[0]), "+f"(c[1]), "+f"(c[2]), "+f"(c[3])
        : "r"(a[0]), "r"(a[1]), "r"(a[2]), "r"(a[3]), "r"(b[0]), "r"(b[1]));
}

__device__ __forceinline__ void gemm_load_stage(
    GemmStage& st, const float* __restrict__ A, const float* __restrict__ B,
    int m0, int n0, int k0, int M, int Ncols, int lda, int ldb, int tid)
{
    // A tile: 128 rows x 16 cols = 512 float4, 2 per thread
#pragma unroll
    for (int r = 0; r < 2; r++) {
        int i = tid + r * 256;
        int row = i >> 2;
        int q = (i & 3) * 4;
        int grow = m0 + row;
        bool p = grow < M;
        int crow = p ? grow : (M - 1);
        cpasync16(&st.As[row][q], A + (size_t)crow * lda + k0 + q, p);
    }
    // B tile: 16 rows x 128 cols = 512 float4, 2 per thread
#pragma unroll
    for (int r = 0; r < 2; r++) {
        int i = tid + r * 256;
        int row = i >> 5;
        int c = (i & 31) * 4;
        bool p = (n0 + c) < Ncols;
        int cc = p ? (n0 + c) : 0;
        cpasync16(&st.Bs[row][c], B + (size_t)(k0 + row) * ldb + cc, p);
    }
    cp_commit();
}

__global__ void __launch_bounds__(256) k_gemm_3xtf32(
    const float* __restrict__ A, const float* __restrict__ B, float* __restrict__ C,
    int M, int K, int Ncols, int lda, int ldb, int ldc)
{
    __shared__ GemmStage stg[2];

    int tid  = threadIdx.x;
    int warp = tid >> 5, lane = tid & 31;
    int wm = warp >> 1, wn = warp & 1;       // 4 x 2 warp grid
    int g = lane >> 2, tq = lane & 3;

    int m0 = blockIdx.x * GBM;
    int n0 = blockIdx.y * GBN;

    float acc[2][8][4];
#pragma unroll
    for (int mt = 0; mt < 2; mt++)
#pragma unroll
        for (int nt = 0; nt < 8; nt++)
#pragma unroll
            for (int r = 0; r < 4; r++) acc[mt][nt][r] = 0.0f;

    int nit = K / GBK;
    gemm_load_stage(stg[0], A, B, m0, n0, 0, M, Ncols, lda, ldb, tid);

    for (int it = 0; it < nit; it++) {
        if (it + 1 < nit) {
            gemm_load_stage(stg[(it + 1) & 1], A, B, m0, n0, (it + 1) * GBK,
                            M, Ncols, lda, ldb, tid);
            cp_wait<1>();
        } else {
            cp_wait<0>();
        }
        __syncthreads();

        GemmStage& s = stg[it & 1];
#pragma unroll
        for (int kk = 0; kk < GBK; kk += 8) {
            uint32_t ahi[2][4], alo[2][4];
#pragma unroll
            for (int mt = 0; mt < 2; mt++) {
                int mb = wm * 32 + mt * 16;
                split_tf32(s.As[mb + g][kk + tq],          ahi[mt][0], alo[mt][0]);
                split_tf32(s.As[mb + 8 + g][kk + tq],      ahi[mt][1], alo[mt][1]);
                split_tf32(s.As[mb + g][kk + tq + 4],      ahi[mt][2], alo[mt][2]);
                split_tf32(s.As[mb + 8 + g][kk + tq + 4],  ahi[mt][3], alo[mt][3]);
            }
            uint32_t bhi[8][2], blo[8][2];
#pragma unroll
            for (int nt = 0; nt < 8; nt++) {
                int nb = wn * 64 + nt * 8 + g;
                split_tf32(s.Bs[kk + tq][nb],     bhi[nt][0], blo[nt][0]);
                split_tf32(s.Bs[kk + tq + 4][nb], bhi[nt][1], blo[nt][1]);
            }
#pragma unroll
            for (int mt = 0; mt < 2; mt++)
#pragma unroll
                for (int nt = 0; nt < 8; nt++) {
                    mma_tf32(acc[mt][nt], alo[mt], bhi[nt]);   // small terms first
                    mma_tf32(acc[mt][nt], ahi[mt], blo[nt]);
                    mma_tf32(acc[mt][nt], ahi[mt], bhi[nt]);
                }
        }
        __syncthreads();
    }

    // epilogue
#pragma unroll
    for (int mt = 0; mt < 2; mt++) {
        int row0 = m0 + wm * 32 + mt * 16 + g;
        int row1 = row0 + 8;
#pragma unroll
        for (int nt = 0; nt < 8; nt++) {
            int col = n0 + wn * 64 + nt * 8 + tq * 2;
            if (col < Ncols) {
                if (row0 < M)
                    *(float2*)(C + (size_t)row0 * ldc + col) =
                        make_float2(acc[mt][nt][0], acc[mt][nt][1]);
                if (row1 < M)
                    *(float2*)(C + (size_t)row1 * ldc + col) =
                        make_float2(acc[mt][nt][2], acc[mt][nt][3]);
            }
        }
    }
}

// ---------------- per-node attention coefficients (warp per node) ----------------
__global__ void k_alpha(const float* __restrict__ htab, int ld, int cdim,
                        const float* __restrict__ asrc, const float* __restrict__ adst,
                        float* __restrict__ out_s, float* __restrict__ out_d)
{
    int warp = (blockIdx.x * blockDim.x + threadIdx.x) >> 5;
    int lane = threadIdx.x & 31;
    if (warp >= NNODES) return;
    const float* hrow = htab + (size_t)warp * ld;
#pragma unroll
    for (int h = 0; h < 4; h++) {
        float s = 0.f, d = 0.f;
        for (int c = lane; c < cdim; c += 32) {
            float v = hrow[h * cdim + c];
            s += v * asrc[h * cdim + c];
            d += v * adst[h * cdim + c];
        }
#pragma unroll
        for (int o = 16; o; o >>= 1) {
            s += __shfl_xor_sync(0xffffffffu, s, o);
            d += __shfl_xor_sync(0xffffffffu, d, o);
        }
        if (lane == 0) {
            out_s[warp * 4 + h] = s;
            out_d[warp * 4 + h] = d;
        }
    }
}

// ---------------- layer-1 aggregation (warp per dst node), fused bias+ELU ----------------
__global__ void k_agg1(const float* __restrict__ htab, const float* __restrict__ as,
                       const float* __restrict__ ad, const float* __restrict__ bias,
                       const int* __restrict__ rowptr, const int* __restrict__ colidx,
                       float* __restrict__ out, int out_off)
{
    int n = (blockIdx.x * blockDim.x + threadIdx.x) >> 5;
    int lane = threadIdx.x & 31;
    if (n >= NNODES) return;
    int s0 = rowptr[n], s1 = rowptr[n + 1];
    float4 ad4 = ((const float4*)ad)[n];

    // pass 1: per-head max logit
    float m0 = -1e30f, m1 = -1e30f, m2 = -1e30f, m3 = -1e30f;
    for (int i = s0 + lane; i < s1; i += 32) {
        int src = colidx[i];
        float4 a = ((const float4*)as)[src];
        m0 = fmaxf(m0, lrelu(a.x + ad4.x));
        m1 = fmaxf(m1, lrelu(a.y + ad4.y));
        m2 = fmaxf(m2, lrelu(a.z + ad4.z));
        m3 = fmaxf(m3, lrelu(a.w + ad4.w));
    }
#pragma unroll
    for (int o = 16; o; o >>= 1) {
        m0 = fmaxf(m0, __shfl_xor_sync(0xffffffffu, m0, o));
        m1 = fmaxf(m1, __shfl_xor_sync(0xffffffffu, m1, o));
        m2 = fmaxf(m2, __shfl_xor_sync(0xffffffffu, m2, o));
        m3 = fmaxf(m3, __shfl_xor_sync(0xffffffffu, m3, o));
    }

    // pass 2: weighted aggregation (unnormalized) + denominator
    float d0 = 0.f, d1 = 0.f, d2 = 0.f, d3 = 0.f;
    float acc0 = 0.f, acc1 = 0.f, acc2 = 0.f, acc3 = 0.f;
    int i = s0;
    for (; i + 1 < s1; i += 2) {
        int srcA = colidx[i];
        int srcB = colidx[i + 1];
        float4 aA = ((const float4*)as)[srcA];
        float4 aB = ((const float4*)as)[srcB];
        const float* hA = htab + (size_t)srcA * LD1;
        const float* hB = htab + (size_t)srcB * LD1;
        float vA0 = hA[lane], vA1 = hA[32 + lane], vA2 = hA[64 + lane], vA3 = hA[96 + lane];
        float vB0 = hB[lane], vB1 = hB[32 + lane], vB2 = hB[64 + lane], vB3 = hB[96 + lane];
        float wA0 = __expf(lrelu(aA.x + ad4.x) - m0);
        float wA1 = __expf(lrelu(aA.y + ad4.y) - m1);
        float wA2 = __expf(lrelu(aA.z + ad4.z) - m2);
        float wA3 = __expf(lrelu(aA.w + ad4.w) - m3);
        float wB0 = __expf(lrelu(aB.x + ad4.x) - m0);
        float wB1 = __expf(lrelu(aB.y + ad4.y) - m1);
        float wB2 = __expf(lrelu(aB.z + ad4.z) - m2);
        float wB3 = __expf(lrelu(aB.w + ad4.w) - m3);
        d0 += wA0 + wB0; d1 += wA1 + wB1; d2 += wA2 + wB2; d3 += wA3 + wB3;
        acc0 += wA0 * vA0 + wB0 * vB0;
        acc1 += wA1 * vA1 + wB1 * vB1;
        acc2 += wA2 * vA2 + wB2 * vB2;
        acc3 += wA3 * vA3 + wB3 * vB3;
    }
    if (i < s1) {
        int src = colidx[i];
        float4 a = ((const float4*)as)[src];
        const float* hr = htab + (size_t)src * LD1;
        float w0 = __expf(lrelu(a.x + ad4.x) - m0);
        float w1 = __expf(lrelu(a.y + ad4.y) - m1);
        float w2 = __expf(lrelu(a.z + ad4.z) - m2);
        float w3 = __expf(lrelu(a.w + ad4.w) - m3);
        d0 += w0; d1 += w1; d2 += w2; d3 += w3;
        acc0 += w0 * hr[lane];
        acc1 += w1 * hr[32 + lane];
        acc2 += w2 * hr[64 + lane];
        acc3 += w3 * hr[96 + lane];
    }

    float* orow = out + (size_t)n * LDCAT + out_off;
    orow[lane]      = eluf(acc0 / (d0 + 1e-16f) + bias[lane]);
    orow[32 + lane] = eluf(acc1 / (d1 + 1e-16f) + bias[32 + lane]);
    orow[64 + lane] = eluf(acc2 / (d2 + 1e-16f) + bias[64 + lane]);
    orow[96 + lane] = eluf(acc3 / (d3 + 1e-16f) + bias[96 + lane]);
}

// ---------------- layer-2 aggregation (warp per dst node), head-mean + bias ----------------
__global__ void k_agg2(const float* __restrict__ htab, const float* __restrict__ as,
                       const float* __restrict__ ad, const float* __restrict__ bias,
                       const int* __restrict__ rowptr, const int* __restrict__ colidx,
                       float* __restrict__ out)
{
    int n = (blockIdx.x * blockDim.x + threadIdx.x) >> 5;
    int lane = threadIdx.x & 31;
    if (n >= NNODES) return;
    int s0 = rowptr[n], s1 = rowptr[n + 1];
    float4 ad4 = ((const float4*)ad)[n];

    float m0 = -1e30f, m1 = -1e30f, m2 = -1e30f, m3 = -1e30f;
    for (int i = s0 + lane; i < s1; i += 32) {
        int src = colidx[i];
        float4 a = ((const float4*)as)[src];
        m0 = fmaxf(m0, lrelu(a.x + ad4.x));
        m1 = fmaxf(m1, lrelu(a.y + ad4.y));
        m2 = fmaxf(m2, lrelu(a.z + ad4.z));
        m3 = fmaxf(m3, lrelu(a.w + ad4.w));
    }
#pragma unroll
    for (int o = 16; o; o >>= 1) {
        m0 = fmaxf(m0, __shfl_xor_sync(0xffffffffu, m0, o));
        m1 = fmaxf(m1, __shfl_xor_sync(0xffffffffu, m1, o));
        m2 = fmaxf(m2, __shfl_xor_sync(0xffffffffu, m2, o));
        m3 = fmaxf(m3, __shfl_xor_sync(0xffffffffu, m3, o));
    }

    float d0 = 0.f, d1 = 0.f, d2 = 0.f, d3 = 0.f;
    float accA0 = 0.f, accA1 = 0.f, accA2 = 0.f, accA3 = 0.f;   // channels 0..31 of each head
    float accB0 = 0.f, accB1 = 0.f, accB2 = 0.f, accB3 = 0.f;   // channels 32..39 (lane < 8)
    bool hasB = lane < 8;
    for (int i = s0; i < s1; i++) {
        int src = colidx[i];
        float4 a = ((const float4*)as)[src];
        const float* hr = htab + (size_t)src * LD2;
        float vA0 = hr[lane], vA1 = hr[40 + lane], vA2 = hr[80 + lane], vA3 = hr[120 + lane];
        float vB0 = 0.f, vB1 = 0.f, vB2 = 0.f, vB3 = 0.f;
        if (hasB) {
            vB0 = hr[32 + lane]; vB1 = hr[72 + lane]; vB2 = hr[112 + lane]; vB3 = hr[152 + lane];
        }
        float w0 = __expf(lrelu(a.x + ad4.x) - m0);
        float w1 = __expf(lrelu(a.y + ad4.y) - m1);
        float w2 = __expf(lrelu(a.z + ad4.z) - m2);
        float w3 = __expf(lrelu(a.w + ad4.w) - m3);
        d0 += w0; d1 += w1; d2 += w2; d3 += w3;
        accA0 += w0 * vA0; accA1 += w1 * vA1; accA2 += w2 * vA2; accA3 += w3 * vA3;
        accB0 += w0 * vB0; accB1 += w1 * vB1; accB2 += w2 * vB2; accB3 += w3 * vB3;
    }
    float i0 = 1.f / (d0 + 1e-16f), i1 = 1.f / (d1 + 1e-16f);
    float i2 = 1.f / (d2 + 1e-16f), i3 = 1.f / (d3 + 1e-16f);
    float* orow = out + (size_t)n * 40;
    orow[lane] = 0.25f * (accA0 * i0 + accA1 * i1 + accA2 * i2 + accA3 * i3) + bias[lane];
    if (hasB)
        orow[32 + lane] =
            0.25f * (accB0 * i0 + accB1 * i1 + accB2 * i2 + accB3 * i3) + bias[32 + lane];
}

// ---------------- launch ----------------
extern "C" void kernel_launch(void* const* d_in, const int* in_sizes, int n_in,
                              void* d_out, int out_size)
{
    const float* x0    = (const float*)d_in[0];
    const float* x1    = (const float*)d_in[1];
    const int*   ei    = (const int*)d_in[2];
    const float* W1_0  = (const float*)d_in[3];
    const float* aS1_0 = (const float*)d_in[4];
    const float* aD1_0 = (const float*)d_in[5];
    const float* b1_0  = (const float*)d_in[6];
    const float* W1_1  = (const float*)d_in[7];
    const float* aS1_1 = (const float*)d_in[8];
    const float* aD1_1 = (const float*)d_in[9];
    const float* b1_1  = (const float*)d_in[10];
    const float* W2    = (const float*)d_in[11];
    const float* aS2   = (const float*)d_in[12];
    const float* aD2   = (const float*)d_in[13];
    const float* b2    = (const float*)d_in[14];
    float* out = (float*)d_out;

    const int* srcp = ei;
    const int* dstp = ei + NEDGES;

    float *bufA, *bufB, *xcat, *pas0, *pad0, *pas1, *pad1;
    int *cnt, *incl, *bsum, *rowptr, *cursor, *colidx;
    cudaGetSymbolAddress((void**)&bufA, g_bufA);
    cudaGetSymbolAddress((void**)&bufB, g_bufB);
    cudaGetSymbolAddress((void**)&xcat, g_xcat);
    cudaGetSymbolAddress((void**)&pas0, g_pas0);
    cudaGetSymbolAddress((void**)&pad0, g_pad0);
    cudaGetSymbolAddress((void**)&pas1, g_pas1);
    cudaGetSymbolAddress((void**)&pad1, g_pad1);
    cudaGetSymbolAddress((void**)&cnt, g_cnt);
    cudaGetSymbolAddress((void**)&incl, g_incl);
    cudaGetSymbolAddress((void**)&bsum, g_bsum);
    cudaGetSymbolAddress((void**)&rowptr, g_rowptr);
    cudaGetSymbolAddress((void**)&cursor, g_cursor);
    cudaGetSymbolAddress((void**)&colidx, g_colidx);

    // CSR build (includes self-loops)
    k_init_cnt<<<(NNODES + 255) / 256, 256>>>(cnt);
    k_hist<<<(NEDGES + 255) / 256, 256>>>(dstp, cnt);
    k_scan1<<<NB_SCAN, 1024>>>(cnt, incl, bsum);
    k_scan2<<<1, 128>>>(bsum);
    k_scan3<<<(NNODES + 255) / 256, 256>>>(incl, bsum, cnt, rowptr, cursor);
    k_scatter<<<(ETOT + 255) / 256, 256>>>(srcp, dstp, cursor, colidx);

    dim3 blk(256);
    dim3 g1((NNODES + GBM - 1) / GBM, 1);
    // layer-1 GEMMs (3xTF32 tensor cores)
    k_gemm_3xtf32<<<g1, blk>>>(x0, W1_0, bufA, NNODES, KDIM, LD1, KDIM, LD1, LD1);
    k_gemm_3xtf32<<<g1, blk>>>(x1, W1_1, bufB, NNODES, KDIM, LD1, KDIM, LD1, LD1);
    // attention coefficients
    k_alpha<<<12500, 256>>>(bufA, LD1, 32, aS1_0, aD1_0, pas0, pad0);
    k_alpha<<<12500, 256>>>(bufB, LD1, 32, aS1_1, aD1_1, pas1, pad1);
    // layer-1 aggregation (+bias +ELU), write into concat buffer
    k_agg1<<<12500, 256>>>(bufA, pas0, pad0, b1_0, rowptr, colidx, xcat, 0);
    k_agg1<<<12500, 256>>>(bufB, pas1, pad1, b1_1, rowptr, colidx, xcat, 128);
    // layer-2 GEMM (reuse bufA as h2 [N,160])
    dim3 g2((NNODES + GBM - 1) / GBM, (LD2 + GBN - 1) / GBN);
    k_gemm_3xtf32<<<g2, blk>>>(xcat, W2, bufA, NNODES, KDIM, LD2, LDCAT, LD2, LD2);
    k_alpha<<<12500, 256>>>(bufA, LD2, 40, aS2, aD2, pas0, pad0);
    // layer-2 aggregation: head mean + bias -> d_out
    k_agg2<<<12500, 256>>>(bufA, pas0, pad0, b2, rowptr, colidx, out);
}

// round 4
// speedup vs baseline: 1.2653x; 1.1017x over previous
#include <cuda_runtime.h>
#include <math.h>
#include <stdint.h>

// Problem constants
#define NNODES 100000
#define NEDGES 1600000
#define ETOT   (NEDGES + NNODES)   // edges + self loops
#define KDIM   256
#define LD1    128                 // HEADS*HID = 4*32
#define LD2    160                 // HEADS2*NCLASS = 4*40
#define LDCAT  256
#define NEG_SLOPE 0.2f

// ---------------- scratch (static device globals; no allocations) --------
__device__ __align__(16) float g_bufA[(size_t)NNODES * LD2];   // h1_0 then h2
__device__ __align__(16) float g_bufB[(size_t)NNODES * LD1];   // h1_1
__device__ __align__(16) float g_xcat[(size_t)NNODES * LDCAT]; // concat(elu out1_0, elu out1_1)
__device__ __align__(16) float g_pas0[NNODES * 4];
__device__ __align__(16) float g_pad0[NNODES * 4];
__device__ __align__(16) float g_pas1[NNODES * 4];
__device__ __align__(16) float g_pad1[NNODES * 4];
__device__ int g_cnt[NNODES];
__device__ int g_incl[NNODES];
__device__ int g_bsum[128];
__device__ int g_rowptr[NNODES + 1];
__device__ int g_cursor[NNODES];
__device__ int g_colidx[ETOT];

// ---------------- helpers ----------------
__device__ __forceinline__ float lrelu(float x) { return fmaxf(x, NEG_SLOPE * x); }
__device__ __forceinline__ float eluf(float x)  { return x > 0.0f ? x : expm1f(x); }

// ---------------- CSR build ----------------
__global__ void k_init_cnt(int* cnt) {
    int i = blockIdx.x * blockDim.x + threadIdx.x;
    if (i < NNODES) cnt[i] = 1;   // self-loop
}

__global__ void k_hist(const int* __restrict__ dst, int* cnt) {
    int e = blockIdx.x * blockDim.x + threadIdx.x;
    if (e < NEDGES) atomicAdd(&cnt[dst[e]], 1);
}

__global__ void k_scan1(const int* __restrict__ cnt, int* incl, int* bsum) {
    __shared__ int sh[1024];
    int i = blockIdx.x * 1024 + threadIdx.x;
    int v = (i < NNODES) ? cnt[i] : 0;
    sh[threadIdx.x] = v;
    __syncthreads();
    for (int off = 1; off < 1024; off <<= 1) {
        int t = (threadIdx.x >= off) ? sh[threadIdx.x - off] : 0;
        __syncthreads();
        sh[threadIdx.x] += t;
        __syncthreads();
    }
    if (i < NNODES) incl[i] = sh[threadIdx.x];
    if (threadIdx.x == 1023) bsum[blockIdx.x] = sh[1023];
}

#define NB_SCAN ((NNODES + 1023) / 1024)   // 98

// fused: every block redundantly scans the 98 block sums, then finalizes rowptr
__global__ void k_scan23(const int* __restrict__ incl, const int* __restrict__ bsum,
                         const int* __restrict__ cnt, int* rowptr, int* cursor) {
    __shared__ int sb[128];
    int t = threadIdx.x;
    if (t < 128) sb[t] = (t < NB_SCAN) ? bsum[t] : 0;
    __syncthreads();
    for (int off = 1; off < 128; off <<= 1) {
        int v = (t >= off && t < 128) ? sb[t - off] : 0;
        __syncthreads();
        if (t < 128) sb[t] += v;
        __syncthreads();
    }
    int i = blockIdx.x * blockDim.x + t;
    if (i >= NNODES) return;
    int blk = i >> 10;
    int off = blk ? sb[blk - 1] : 0;
    int inc = incl[i] + off;
    int start = inc - cnt[i];
    rowptr[i] = start;
    cursor[i] = start;
    if (i == NNODES - 1) rowptr[NNODES] = inc;
}

__global__ void k_scatter(const int* __restrict__ src, const int* __restrict__ dst,
                          int* cursor, int* colidx) {
    int e = blockIdx.x * blockDim.x + threadIdx.x;
    if (e < NEDGES) {
        int d = dst[e];
        int p = atomicAdd(&cursor[d], 1);
        colidx[p] = src[e];
    } else if (e < ETOT) {
        int n = e - NEDGES;
        int p = atomicAdd(&cursor[n], 1);
        colidx[p] = n;
    }
}

// ================= 3xTF32 tensor-core GEMM (fp32-accurate) =================
#define GBM 128
#define GBN 128
#define GBK 16

struct GemmStage {
    float As[GBM][GBK + 4];
    float Bs[GBK][GBN + 8];
};

__device__ __forceinline__ void cpasync16(void* dst, const void* src, bool pred) {
    uint32_t d = (uint32_t)__cvta_generic_to_shared(dst);
    int sz = pred ? 16 : 0;
    asm volatile("cp.async.cg.shared.global [%0], [%1], 16, %2;\n"
                 :: "r"(d), "l"(src), "r"(sz));
}
__device__ __forceinline__ void cp_commit() {
    asm volatile("cp.async.commit_group;\n");
}
template <int NWAIT>
__device__ __forceinline__ void cp_wait() {
    asm volatile("cp.async.wait_group %0;\n" :: "n"(NWAIT));
}

__device__ __forceinline__ uint32_t f2tf32(float x) {
    uint32_t r;
    asm("cvt.rna.tf32.f32 %0, %1;\n" : "=r"(r) : "f"(x));
    return r;
}
__device__ __forceinline__ void split_tf32(float x, uint32_t& hi, uint32_t& lo) {
    hi = f2tf32(x);
    lo = f2tf32(x - __uint_as_float(hi));
}

__device__ __forceinline__ void mma_tf32(float* c, const uint32_t* a, const uint32_t* b) {
    asm volatile(
        "mma.sync.aligned.m16n8k8.row.col.f32.tf32.tf32.f32 "
        "{%0,%1,%2,%3}, {%4,%5,%6,%7}, {%8,%9}, {%0,%1,%2,%3};\n"
        : "+f"(c[0]), "+f"(c[1]), "+f"(c[2]), "+f"(c[3])
        : "r"(a[0]), "r"(a[1]), "r"(a[2]), "r"(a[3]), "r"(b[0]), "r"(b[1]));
}

__device__ __forceinline__ void gemm_load_stage(
    GemmStage& st, const float* __restrict__ A, const float* __restrict__ B,
    int m0, int n0, int k0, int M, int Ncols, int lda, int ldb, int tid)
{
#pragma unroll
    for (int r = 0; r < 2; r++) {
        int i = tid + r * 256;
        int row = i >> 2;
        int q = (i & 3) * 4;
        int grow = m0 + row;
        bool p = grow < M;
        int crow = p ? grow : (M - 1);
        cpasync16(&st.As[row][q], A + (size_t)crow * lda + k0 + q, p);
    }
#pragma unroll
    for (int r = 0; r < 2; r++) {
        int i = tid + r * 256;
        int row = i >> 5;
        int c = (i & 31) * 4;
        bool p = (n0 + c) < Ncols;
        int cc = p ? (n0 + c) : 0;
        cpasync16(&st.Bs[row][c], B + (size_t)(k0 + row) * ldb + cc, p);
    }
    cp_commit();
}

__global__ void __launch_bounds__(256) k_gemm_3xtf32(
    const float* __restrict__ A, const float* __restrict__ B, float* __restrict__ C,
    int M, int K, int Ncols, int lda, int ldb, int ldc)
{
    __shared__ GemmStage stg[2];

    int tid  = threadIdx.x;
    int warp = tid >> 5, lane = tid & 31;
    int wm = warp >> 1, wn = warp & 1;
    int g = lane >> 2, tq = lane & 3;

    int m0 = blockIdx.x * GBM;
    int n0 = blockIdx.y * GBN;

    float acc[2][8][4];
#pragma unroll
    for (int mt = 0; mt < 2; mt++)
#pragma unroll
        for (int nt = 0; nt < 8; nt++)
#pragma unroll
            for (int r = 0; r < 4; r++) acc[mt][nt][r] = 0.0f;

    int nit = K / GBK;
    gemm_load_stage(stg[0], A, B, m0, n0, 0, M, Ncols, lda, ldb, tid);

    for (int it = 0; it < nit; it++) {
        if (it + 1 < nit) {
            gemm_load_stage(stg[(it + 1) & 1], A, B, m0, n0, (it + 1) * GBK,
                            M, Ncols, lda, ldb, tid);
            cp_wait<1>();
        } else {
            cp_wait<0>();
        }
        __syncthreads();

        GemmStage& s = stg[it & 1];
#pragma unroll
        for (int kk = 0; kk < GBK; kk += 8) {
            uint32_t ahi[2][4], alo[2][4];
#pragma unroll
            for (int mt = 0; mt < 2; mt++) {
                int mb = wm * 32 + mt * 16;
                split_tf32(s.As[mb + g][kk + tq],          ahi[mt][0], alo[mt][0]);
                split_tf32(s.As[mb + 8 + g][kk + tq],      ahi[mt][1], alo[mt][1]);
                split_tf32(s.As[mb + g][kk + tq + 4],      ahi[mt][2], alo[mt][2]);
                split_tf32(s.As[mb + 8 + g][kk + tq + 4],  ahi[mt][3], alo[mt][3]);
            }
            uint32_t bhi[8][2], blo[8][2];
#pragma unroll
            for (int nt = 0; nt < 8; nt++) {
                int nb = wn * 64 + nt * 8 + g;
                split_tf32(s.Bs[kk + tq][nb],     bhi[nt][0], blo[nt][0]);
                split_tf32(s.Bs[kk + tq + 4][nb], bhi[nt][1], blo[nt][1]);
            }
#pragma unroll
            for (int mt = 0; mt < 2; mt++)
#pragma unroll
                for (int nt = 0; nt < 8; nt++) {
                    mma_tf32(acc[mt][nt], alo[mt], bhi[nt]);
                    mma_tf32(acc[mt][nt], ahi[mt], blo[nt]);
                    mma_tf32(acc[mt][nt], ahi[mt], bhi[nt]);
                }
        }
        __syncthreads();
    }

#pragma unroll
    for (int mt = 0; mt < 2; mt++) {
        int row0 = m0 + wm * 32 + mt * 16 + g;
        int row1 = row0 + 8;
#pragma unroll
        for (int nt = 0; nt < 8; nt++) {
            int col = n0 + wn * 64 + nt * 8 + tq * 2;
            if (col < Ncols) {
                if (row0 < M)
                    *(float2*)(C + (size_t)row0 * ldc + col) =
                        make_float2(acc[mt][nt][0], acc[mt][nt][1]);
                if (row1 < M)
                    *(float2*)(C + (size_t)row1 * ldc + col) =
                        make_float2(acc[mt][nt][2], acc[mt][nt][3]);
            }
        }
    }
}

// ---------------- per-node attention coefficients (warp per node) ----------------
__global__ void k_alpha(const float* __restrict__ htab, int ld, int cdim,
                        const float* __restrict__ asrc, const float* __restrict__ adst,
                        float* __restrict__ out_s, float* __restrict__ out_d)
{
    int warp = (blockIdx.x * blockDim.x + threadIdx.x) >> 5;
    int lane = threadIdx.x & 31;
    if (warp >= NNODES) return;
    const float* hrow = htab + (size_t)warp * ld;
#pragma unroll
    for (int h = 0; h < 4; h++) {
        float s = 0.f, d = 0.f;
        for (int c = lane; c < cdim; c += 32) {
            float v = hrow[h * cdim + c];
            s += v * asrc[h * cdim + c];
            d += v * adst[h * cdim + c];
        }
#pragma unroll
        for (int o = 16; o; o >>= 1) {
            s += __shfl_xor_sync(0xffffffffu, s, o);
            d += __shfl_xor_sync(0xffffffffu, d, o);
        }
        if (lane == 0) {
            out_s[warp * 4 + h] = s;
            out_d[warp * 4 + h] = d;
        }
    }
}

// ---------------- layer-1 aggregation: warp/node, lane-parallel weights, no max pass ----
__global__ void k_agg1(const float* __restrict__ htab, const float* __restrict__ as,
                       const float* __restrict__ ad, const float* __restrict__ bias,
                       const int* __restrict__ rowptr, const int* __restrict__ colidx,
                       float* __restrict__ out, int out_off)
{
    int n = (blockIdx.x * blockDim.x + threadIdx.x) >> 5;
    int lane = threadIdx.x & 31;
    if (n >= NNODES) return;
    int s0 = rowptr[n], s1 = rowptr[n + 1];
    float4 ad4 = ((const float4*)ad)[n];
    int head = lane >> 3;   // lane holds channels 4*lane..4*lane+3 (all in one head)

    float4 acc = make_float4(0.f, 0.f, 0.f, 0.f);
    float4 dac = make_float4(0.f, 0.f, 0.f, 0.f);

    for (int base = s0; base < s1; base += 32) {
        int i = base + lane;
        int src = 0;
        float4 w4 = make_float4(0.f, 0.f, 0.f, 0.f);
        if (i < s1) {
            src = colidx[i];
            float4 a = ((const float4*)as)[src];
            w4.x = __expf(lrelu(a.x + ad4.x));
            w4.y = __expf(lrelu(a.y + ad4.y));
            w4.z = __expf(lrelu(a.z + ad4.z));
            w4.w = __expf(lrelu(a.w + ad4.w));
            dac.x += w4.x; dac.y += w4.y; dac.z += w4.z; dac.w += w4.w;
        }
        int cnt = min(32, s1 - base);
        int j = 0;
        for (; j + 1 < cnt; j += 2) {
            int sA = __shfl_sync(0xffffffffu, src, j);
            int sB = __shfl_sync(0xffffffffu, src, j + 1);
            float a0 = __shfl_sync(0xffffffffu, w4.x, j);
            float a1 = __shfl_sync(0xffffffffu, w4.y, j);
            float a2 = __shfl_sync(0xffffffffu, w4.z, j);
            float a3 = __shfl_sync(0xffffffffu, w4.w, j);
            float b0 = __shfl_sync(0xffffffffu, w4.x, j + 1);
            float b1 = __shfl_sync(0xffffffffu, w4.y, j + 1);
            float b2 = __shfl_sync(0xffffffffu, w4.z, j + 1);
            float b3 = __shfl_sync(0xffffffffu, w4.w, j + 1);
            float wA = head == 0 ? a0 : head == 1 ? a1 : head == 2 ? a2 : a3;
            float wB = head == 0 ? b0 : head == 1 ? b1 : head == 2 ? b2 : b3;
            float4 hA = ((const float4*)(htab + (size_t)sA * LD1))[lane];
            float4 hB = ((const float4*)(htab + (size_t)sB * LD1))[lane];
            acc.x += wA * hA.x + wB * hB.x;
            acc.y += wA * hA.y + wB * hB.y;
            acc.z += wA * hA.z + wB * hB.z;
            acc.w += wA * hA.w + wB * hB.w;
        }
        if (j < cnt) {
            int sA = __shfl_sync(0xffffffffu, src, j);
            float a0 = __shfl_sync(0xffffffffu, w4.x, j);
            float a1 = __shfl_sync(0xffffffffu, w4.y, j);
            float a2 = __shfl_sync(0xffffffffu, w4.z, j);
            float a3 = __shfl_sync(0xffffffffu, w4.w, j);
            float wA = head == 0 ? a0 : head == 1 ? a1 : head == 2 ? a2 : a3;
            float4 hA = ((const float4*)(htab + (size_t)sA * LD1))[lane];
            acc.x += wA * hA.x;
            acc.y += wA * hA.y;
            acc.z += wA * hA.z;
            acc.w += wA * hA.w;
        }
    }

#pragma unroll
    for (int o = 16; o; o >>= 1) {
        dac.x += __shfl_xor_sync(0xffffffffu, dac.x, o);
        dac.y += __shfl_xor_sync(0xffffffffu, dac.y, o);
        dac.z += __shfl_xor_sync(0xffffffffu, dac.z, o);
        dac.w += __shfl_xor_sync(0xffffffffu, dac.w, o);
    }
    float d = head == 0 ? dac.x : head == 1 ? dac.y : head == 2 ? dac.z : dac.w;
    float inv = 1.f / (d + 1e-16f);
    float4 b4 = ((const float4*)bias)[lane];
    float4 o4;
    o4.x = eluf(acc.x * inv + b4.x);
    o4.y = eluf(acc.y * inv + b4.y);
    o4.z = eluf(acc.z * inv + b4.z);
    o4.w = eluf(acc.w * inv + b4.w);
    ((float4*)(out + (size_t)n * LDCAT + out_off))[lane] = o4;
}

// ---------------- layer-2 aggregation: warp/node, lane-parallel weights, no max pass ----
__global__ void k_agg2(const float* __restrict__ htab, const float* __restrict__ as,
                       const float* __restrict__ ad, const float* __restrict__ bias,
                       const int* __restrict__ rowptr, const int* __restrict__ colidx,
                       float* __restrict__ out)
{
    int n = (blockIdx.x * blockDim.x + threadIdx.x) >> 5;
    int lane = threadIdx.x & 31;
    if (n >= NNODES) return;
    int s0 = rowptr[n], s1 = rowptr[n + 1];
    float4 ad4 = ((const float4*)ad)[n];
    bool hasB = lane < 8;

    float4 dac = make_float4(0.f, 0.f, 0.f, 0.f);
    float accA0 = 0.f, accA1 = 0.f, accA2 = 0.f, accA3 = 0.f;
    float accB0 = 0.f, accB1 = 0.f, accB2 = 0.f, accB3 = 0.f;

    for (int base = s0; base < s1; base += 32) {
        int i = base + lane;
        int src = 0;
        float4 w4 = make_float4(0.f, 0.f, 0.f, 0.f);
        if (i < s1) {
            src = colidx[i];
            float4 a = ((const float4*)as)[src];
            w4.x = __expf(lrelu(a.x + ad4.x));
            w4.y = __expf(lrelu(a.y + ad4.y));
            w4.z = __expf(lrelu(a.z + ad4.z));
            w4.w = __expf(lrelu(a.w + ad4.w));
            dac.x += w4.x; dac.y += w4.y; dac.z += w4.z; dac.w += w4.w;
        }
        int cnt = min(32, s1 - base);
        for (int j = 0; j < cnt; j++) {
            int s = __shfl_sync(0xffffffffu, src, j);
            float w0 = __shfl_sync(0xffffffffu, w4.x, j);
            float w1 = __shfl_sync(0xffffffffu, w4.y, j);
            float w2 = __shfl_sync(0xffffffffu, w4.z, j);
            float w3 = __shfl_sync(0xffffffffu, w4.w, j);
            const float* hr = htab + (size_t)s * LD2;
            accA0 += w0 * hr[lane];
            accA1 += w1 * hr[40 + lane];
            accA2 += w2 * hr[80 + lane];
            accA3 += w3 * hr[120 + lane];
            if (hasB) {
                accB0 += w0 * hr[32 + lane];
                accB1 += w1 * hr[72 + lane];
                accB2 += w2 * hr[112 + lane];
                accB3 += w3 * hr[152 + lane];
            }
        }
    }

#pragma unroll
    for (int o = 16; o; o >>= 1) {
        dac.x += __shfl_xor_sync(0xffffffffu, dac.x, o);
        dac.y += __shfl_xor_sync(0xffffffffu, dac.y, o);
        dac.z += __shfl_xor_sync(0xffffffffu, dac.z, o);
        dac.w += __shfl_xor_sync(0xffffffffu, dac.w, o);
    }
    float i0 = 1.f / (dac.x + 1e-16f), i1 = 1.f / (dac.y + 1e-16f);
    float i2 = 1.f / (dac.z + 1e-16f), i3 = 1.f / (dac.w + 1e-16f);
    float* orow = out + (size_t)n * 40;
    orow[lane] = 0.25f * (accA0 * i0 + accA1 * i1 + accA2 * i2 + accA3 * i3) + bias[lane];
    if (hasB)
        orow[32 + lane] =
            0.25f * (accB0 * i0 + accB1 * i1 + accB2 * i2 + accB3 * i3) + bias[32 + lane];
}

// ---------------- launch ----------------
extern "C" void kernel_launch(void* const* d_in, const int* in_sizes, int n_in,
                              void* d_out, int out_size)
{
    const float* x0    = (const float*)d_in[0];
    const float* x1    = (const float*)d_in[1];
    const int*   ei    = (const int*)d_in[2];
    const float* W1_0  = (const float*)d_in[3];
    const float* aS1_0 = (const float*)d_in[4];
    const float* aD1_0 = (const float*)d_in[5];
    const float* b1_0  = (const float*)d_in[6];
    const float* W1_1  = (const float*)d_in[7];
    const float* aS1_1 = (const float*)d_in[8];
    const float* aD1_1 = (const float*)d_in[9];
    const float* b1_1  = (const float*)d_in[10];
    const float* W2    = (const float*)d_in[11];
    const float* aS2   = (const float*)d_in[12];
    const float* aD2   = (const float*)d_in[13];
    const float* b2    = (const float*)d_in[14];
    float* out = (float*)d_out;

    const int* srcp = ei;
    const int* dstp = ei + NEDGES;

    float *bufA, *bufB, *xcat, *pas0, *pad0, *pas1, *pad1;
    int *cnt, *incl, *bsum, *rowptr, *cursor, *colidx;
    cudaGetSymbolAddress((void**)&bufA, g_bufA);
    cudaGetSymbolAddress((void**)&bufB, g_bufB);
    cudaGetSymbolAddress((void**)&xcat, g_xcat);
    cudaGetSymbolAddress((void**)&pas0, g_pas0);
    cudaGetSymbolAddress((void**)&pad0, g_pad0);
    cudaGetSymbolAddress((void**)&pas1, g_pas1);
    cudaGetSymbolAddress((void**)&pad1, g_pad1);
    cudaGetSymbolAddress((void**)&cnt, g_cnt);
    cudaGetSymbolAddress((void**)&incl, g_incl);
    cudaGetSymbolAddress((void**)&bsum, g_bsum);
    cudaGetSymbolAddress((void**)&rowptr, g_rowptr);
    cudaGetSymbolAddress((void**)&cursor, g_cursor);
    cudaGetSymbolAddress((void**)&colidx, g_colidx);

    // CSR build (includes self-loops)
    k_init_cnt<<<(NNODES + 255) / 256, 256>>>(cnt);
    k_hist<<<(NEDGES + 255) / 256, 256>>>(dstp, cnt);
    k_scan1<<<NB_SCAN, 1024>>>(cnt, incl, bsum);
    k_scan23<<<(NNODES + 255) / 256, 256>>>(incl, bsum, cnt, rowptr, cursor);
    k_scatter<<<(ETOT + 255) / 256, 256>>>(srcp, dstp, cursor, colidx);

    dim3 blk(256);
    dim3 g1((NNODES + GBM - 1) / GBM, 1);
    // layer-1 GEMMs (3xTF32 tensor cores) — this one is launch #5, ncu target
    k_gemm_3xtf32<<<g1, blk>>>(x0, W1_0, bufA, NNODES, KDIM, LD1, KDIM, LD1, LD1);
    k_gemm_3xtf32<<<g1, blk>>>(x1, W1_1, bufB, NNODES, KDIM, LD1, KDIM, LD1, LD1);
    // attention coefficients
    k_alpha<<<12500, 256>>>(bufA, LD1, 32, aS1_0, aD1_0, pas0, pad0);
    k_alpha<<<12500, 256>>>(bufB, LD1, 32, aS1_1, aD1_1, pas1, pad1);
    // layer-1 aggregation (+bias +ELU), write into concat buffer
    k_agg1<<<12500, 256>>>(bufA, pas0, pad0, b1_0, rowptr, colidx, xcat, 0);
    k_agg1<<<12500, 256>>>(bufB, pas1, pad1, b1_1, rowptr, colidx, xcat, 128);
    // layer-2 GEMM (reuse bufA as h2 [N,160])
    dim3 g2((NNODES + GBM - 1) / GBM, (LD2 + GBN - 1) / GBN);
    k_gemm_3xtf32<<<g2, blk>>>(xcat, W2, bufA, NNODES, KDIM, LD2, LDCAT, LD2, LD2);
    k_alpha<<<12500, 256>>>(bufA, LD2, 40, aS2, aD2, pas0, pad0);
    // layer-2 aggregation: head mean + bias -> d_out
    k_agg2<<<12500, 256>>>(bufA, pas0, pad0, b2, rowptr, colidx, out);
}